// round 17
// baseline (speedup 1.0000x reference)
#include <cuda_runtime.h>
#include <cuda_bf16.h>
#include <cstdint>

#define Sn 512
#define Bn 64
#define En 256
#define Hn 128
#define G4H 512
#define Tn 128
#define Cv 32000

#define WC_STRIDE 400
#define WA_STRIDE 144
#define VA_STRIDE 144
#define DEC_DYN_SMEM (128*WC_STRIDE*2 + 256*WA_STRIDE*2 + 128*VA_STRIDE*2)   // 212992
#define ENC_DYN_SMEM (G4H * 128 * 2)                                          // 131072

// ---------------- scratch (static device globals; no allocation) ----------------
__device__ float g_xpre[2][Sn][Bn][G4H];
__device__ float g_hs[Sn][Bn][2*Hn];
__device__ __nv_bfloat16 g_hsT_bf[Bn][2*Hn][Sn];   // bf16 transposed encoder outputs
__device__ __nv_bfloat16 g_wahsT_bf[Bn][Sn][Hn];   // bf16 attention precompute
__device__ __nv_bfloat16 g_Wbf[G4H][384];          // bf16 decoder weights [Whh|Wih]
__device__ __nv_bfloat16 g_eWbf[2][G4H][128];      // bf16 encoder Whh (both dirs)
__device__ float g_sfin[Bn][Hn];
__device__ float g_ctx[Bn][2*Hn];
__device__ float g_rowstat[Bn][2];

__device__ __forceinline__ float sigf(float x) { return 1.f / (1.f + __expf(-x)); }
__device__ __forceinline__ float tanh_fast(float x) {
    float y; asm("tanh.approx.f32 %0, %1;" : "=f"(y) : "f"(x)); return y;
}
__device__ __forceinline__ float gred8(float v) {
    v += __shfl_xor_sync(0xFFFFFFFFu, v, 1);
    v += __shfl_xor_sync(0xFFFFFFFFu, v, 2);
    v += __shfl_xor_sync(0xFFFFFFFFu, v, 4);
    return v;
}
__device__ __forceinline__ float dot8(uint4 w, float4 x0, float4 x1) {
    float2 f0 = __bfloat1622float2(*reinterpret_cast<__nv_bfloat162*>(&w.x));
    float2 f1 = __bfloat1622float2(*reinterpret_cast<__nv_bfloat162*>(&w.y));
    float2 f2 = __bfloat1622float2(*reinterpret_cast<__nv_bfloat162*>(&w.z));
    float2 f3 = __bfloat1622float2(*reinterpret_cast<__nv_bfloat162*>(&w.w));
    return f0.x*x0.x + f0.y*x0.y + f1.x*x0.z + f1.y*x0.w
         + f2.x*x1.x + f2.y*x1.y + f3.x*x1.z + f3.y*x1.w;
}
__device__ __forceinline__ float tdot8(uint4 w, float4 v0, float4 v1, float4 u0, float4 u1) {
    float2 f0 = __bfloat1622float2(*reinterpret_cast<__nv_bfloat162*>(&w.x));
    float2 f1 = __bfloat1622float2(*reinterpret_cast<__nv_bfloat162*>(&w.y));
    float2 f2 = __bfloat1622float2(*reinterpret_cast<__nv_bfloat162*>(&w.z));
    float2 f3 = __bfloat1622float2(*reinterpret_cast<__nv_bfloat162*>(&w.w));
    return tanh_fast(f0.x+v0.x)*u0.x + tanh_fast(f0.y+v0.y)*u0.y
         + tanh_fast(f1.x+v0.z)*u0.z + tanh_fast(f1.y+v0.w)*u0.w
         + tanh_fast(f2.x+v1.x)*u1.x + tanh_fast(f2.y+v1.y)*u1.y
         + tanh_fast(f3.x+v1.z)*u1.z + tanh_fast(f3.y+v1.w)*u1.w;
}

// ---------------- cluster / DSMEM helpers -------------------------------------------
__device__ __forceinline__ uint32_t smem_u32(const void* p) {
    uint32_t a;
    asm("{ .reg .u64 t; cvta.to.shared.u64 t, %1; cvt.u32.u64 %0, t; }" : "=r"(a) : "l"(p));
    return a;
}
__device__ __forceinline__ uint32_t mapa_peer(uint32_t a, uint32_t rank) {
    uint32_t r; asm("mapa.shared::cluster.u32 %0, %1, %2;" : "=r"(r) : "r"(a), "r"(rank));
    return r;
}
__device__ __forceinline__ void st_remote_f32(uint32_t a, float v) {
    asm volatile("st.shared::cluster.f32 [%0], %1;" :: "r"(a), "f"(v) : "memory");
}
__device__ __forceinline__ void cluster_barrier() {
    asm volatile("barrier.cluster.arrive.aligned;" ::: "memory");
    asm volatile("barrier.cluster.wait.aligned;" ::: "memory");
}

// ---------------- prep: bf16 conversions ---------------------------------------------
__global__ void prep_bf16(const float* __restrict__ Wih, const float* __restrict__ Whh,
                          const float* __restrict__ eWhh_f, const float* __restrict__ eWhh_b)
{
    int i = blockIdx.x * 256 + threadIdx.x;
    if (i < G4H * 384) {
        int r = i / 384, c = i - r * 384;
        float v = (c < 128) ? Whh[r * 128 + c] : Wih[r * 256 + (c - 128)];
        g_Wbf[r][c] = __float2bfloat16(v);
    }
    if (i < G4H * 128) {
        (&g_eWbf[0][0][0])[i] = __float2bfloat16(eWhh_f[i]);
        (&g_eWbf[1][0][0])[i] = __float2bfloat16(eWhh_b[i]);
    }
}

// ================= fast SGEMM core: 128x128 tile, BK=8, 8x8 microtile ================
#define SG_PAD 132

__global__ void __launch_bounds__(256, 2) sgemm_xpre(
    const float* __restrict__ A,
    const float* __restrict__ B0, const float* __restrict__ B1,
    const float* __restrict__ bi0, const float* __restrict__ bh0,
    const float* __restrict__ bi1, const float* __restrict__ bh1,
    float* __restrict__ Cbase)
{
    int dir = blockIdx.z;
    const float* __restrict__ B  = dir ? B1 : B0;
    const float* __restrict__ bi = dir ? bi1 : bi0;
    const float* __restrict__ bh = dir ? bh1 : bh0;
    float* __restrict__ C = Cbase + (size_t)dir * Sn * Bn * G4H;
    const int K = En;

    __shared__ __align__(16) float As[2][8][SG_PAD];
    __shared__ __align__(16) float Bs[2][8][SG_PAD];

    int tid = threadIdx.x;
    int tx = tid & 15, ty = tid >> 4;
    int m0 = blockIdx.y * 128, n0 = blockIdx.x * 128;
    int lrow = tid >> 1, lk = (tid & 1) * 4;

    const float* Aload = A + (size_t)(m0 + lrow) * K + lk;
    const float* Bload = B + (size_t)(n0 + lrow) * K + lk;

    float acc[8][8] = {};
    float4 ra = *reinterpret_cast<const float4*>(Aload);
    float4 rb = *reinterpret_cast<const float4*>(Bload);
    As[0][lk+0][lrow]=ra.x; As[0][lk+1][lrow]=ra.y; As[0][lk+2][lrow]=ra.z; As[0][lk+3][lrow]=ra.w;
    Bs[0][lk+0][lrow]=rb.x; Bs[0][lk+1][lrow]=rb.y; Bs[0][lk+2][lrow]=rb.z; Bs[0][lk+3][lrow]=rb.w;
    __syncthreads();

    int nkb = K >> 3, buf = 0;
    for (int kb = 0; kb < nkb; kb++) {
        if (kb + 1 < nkb) {
            ra = *reinterpret_cast<const float4*>(Aload + (kb + 1) * 8);
            rb = *reinterpret_cast<const float4*>(Bload + (kb + 1) * 8);
        }
#pragma unroll
        for (int k = 0; k < 8; k++) {
            float4 a0 = *reinterpret_cast<const float4*>(&As[buf][k][ty * 4]);
            float4 a1 = *reinterpret_cast<const float4*>(&As[buf][k][ty * 4 + 64]);
            float4 b0 = *reinterpret_cast<const float4*>(&Bs[buf][k][tx * 4]);
            float4 b1 = *reinterpret_cast<const float4*>(&Bs[buf][k][tx * 4 + 64]);
            float av[8] = {a0.x,a0.y,a0.z,a0.w,a1.x,a1.y,a1.z,a1.w};
            float bv[8] = {b0.x,b0.y,b0.z,b0.w,b1.x,b1.y,b1.z,b1.w};
#pragma unroll
            for (int i = 0; i < 8; i++)
#pragma unroll
                for (int j = 0; j < 8; j++)
                    acc[i][j] += av[i] * bv[j];
        }
        if (kb + 1 < nkb) {
            int nb = buf ^ 1;
            As[nb][lk+0][lrow]=ra.x; As[nb][lk+1][lrow]=ra.y; As[nb][lk+2][lrow]=ra.z; As[nb][lk+3][lrow]=ra.w;
            Bs[nb][lk+0][lrow]=rb.x; Bs[nb][lk+1][lrow]=rb.y; Bs[nb][lk+2][lrow]=rb.z; Bs[nb][lk+3][lrow]=rb.w;
        }
        __syncthreads();
        buf ^= 1;
    }
#pragma unroll
    for (int i = 0; i < 8; i++) {
        int row = m0 + ((i < 4) ? (ty * 4 + i) : (64 + ty * 4 + i - 4));
#pragma unroll
        for (int jh = 0; jh < 2; jh++) {
            int col = n0 + tx * 4 + jh * 64;
            float4 v;
            v.x = acc[i][jh*4+0] + bi[col+0] + bh[col+0];
            v.y = acc[i][jh*4+1] + bi[col+1] + bh[col+1];
            v.z = acc[i][jh*4+2] + bi[col+2] + bh[col+2];
            v.w = acc[i][jh*4+3] + bi[col+3] + bh[col+3];
            *reinterpret_cast<float4*>(&C[(size_t)row * G4H + col]) = v;
        }
    }
}

__global__ void __launch_bounds__(256, 2) sgemm_wahsT(
    const float* __restrict__ A, const float* __restrict__ B)
{
    const int K = 2 * Hn;

    __shared__ __align__(16) float As[2][8][SG_PAD];
    __shared__ __align__(16) float Bs[2][8][SG_PAD];

    int tid = threadIdx.x;
    int tx = tid & 15, ty = tid >> 4;
    int m0 = blockIdx.y * 128;
    int lrow = tid >> 1, lk = (tid & 1) * 4;

    const float* Aload = A + (size_t)(m0 + lrow) * K + lk;
    const float* Bload = B + (size_t)lrow * K + lk;

    float acc[8][8] = {};
    float4 ra = *reinterpret_cast<const float4*>(Aload);
    float4 rb = *reinterpret_cast<const float4*>(Bload);
    As[0][lk+0][lrow]=ra.x; As[0][lk+1][lrow]=ra.y; As[0][lk+2][lrow]=ra.z; As[0][lk+3][lrow]=ra.w;
    Bs[0][lk+0][lrow]=rb.x; Bs[0][lk+1][lrow]=rb.y; Bs[0][lk+2][lrow]=rb.z; Bs[0][lk+3][lrow]=rb.w;
    __syncthreads();

    int nkb = K >> 3, buf = 0;
    for (int kb = 0; kb < nkb; kb++) {
        if (kb + 1 < nkb) {
            ra = *reinterpret_cast<const float4*>(Aload + (kb + 1) * 8);
            rb = *reinterpret_cast<const float4*>(Bload + (kb + 1) * 8);
        }
#pragma unroll
        for (int k = 0; k < 8; k++) {
            float4 a0 = *reinterpret_cast<const float4*>(&As[buf][k][ty * 4]);
            float4 a1 = *reinterpret_cast<const float4*>(&As[buf][k][ty * 4 + 64]);
            float4 b0 = *reinterpret_cast<const float4*>(&Bs[buf][k][tx * 4]);
            float4 b1 = *reinterpret_cast<const float4*>(&Bs[buf][k][tx * 4 + 64]);
            float av[8] = {a0.x,a0.y,a0.z,a0.w,a1.x,a1.y,a1.z,a1.w};
            float bv[8] = {b0.x,b0.y,b0.z,b0.w,b1.x,b1.y,b1.z,b1.w};
#pragma unroll
            for (int i = 0; i < 8; i++)
#pragma unroll
                for (int j = 0; j < 8; j++)
                    acc[i][j] += av[i] * bv[j];
        }
        if (kb + 1 < nkb) {
            int nb = buf ^ 1;
            As[nb][lk+0][lrow]=ra.x; As[nb][lk+1][lrow]=ra.y; As[nb][lk+2][lrow]=ra.z; As[nb][lk+3][lrow]=ra.w;
            Bs[nb][lk+0][lrow]=rb.x; Bs[nb][lk+1][lrow]=rb.y; Bs[nb][lk+2][lrow]=rb.z; Bs[nb][lk+3][lrow]=rb.w;
        }
        __syncthreads();
        buf ^= 1;
    }
#pragma unroll
    for (int i = 0; i < 8; i++) {
        int row = m0 + ((i < 4) ? (ty * 4 + i) : (64 + ty * 4 + i - 4));
        int s = row >> 6, bb = row & 63;
#pragma unroll
        for (int jh = 0; jh < 2; jh++) {
            int col = tx * 4 + jh * 64;
#pragma unroll
            for (int e = 0; e < 4; e++)
                g_wahsT_bf[bb][s][col + e] = __float2bfloat16(acc[i][jh*4+e]);
        }
    }
}

// ---------------- fused logits GEMM ---------------------------------------------------
__global__ void gemm_logits(const float* __restrict__ A1, const float* __restrict__ B1,
                            const float* __restrict__ A2, const float* __restrict__ B2,
                            float* __restrict__ C)
{
    __shared__ __align__(16) float As[16][64];
    __shared__ __align__(16) float Bs[16][64];
    int tid = threadIdx.x;
    int tx = tid & 15, ty = tid >> 4;
    int n0 = blockIdx.x * 64;
    float acc[4][4] = {};

    for (int k0 = 0; k0 < Hn; k0 += 16) {
#pragma unroll
        for (int qq = 0; qq < 4; qq++) {
            int idx = tid + qq * 256;
            int kk = idx & 15, m = idx >> 4;
            As[kk][m] = A1[m * Hn + k0 + kk];
            Bs[kk][m] = B1[(n0 + m) * Hn + k0 + kk];
        }
        __syncthreads();
#pragma unroll
        for (int kk = 0; kk < 16; kk++) {
            float4 a4 = *reinterpret_cast<const float4*>(&As[kk][ty * 4]);
            float4 b4 = *reinterpret_cast<const float4*>(&Bs[kk][tx * 4]);
            float av[4] = {a4.x, a4.y, a4.z, a4.w};
            float bv[4] = {b4.x, b4.y, b4.z, b4.w};
#pragma unroll
            for (int i = 0; i < 4; i++)
#pragma unroll
                for (int j = 0; j < 4; j++)
                    acc[i][j] += av[i] * bv[j];
        }
        __syncthreads();
    }
    for (int k0 = 0; k0 < 2 * Hn; k0 += 16) {
#pragma unroll
        for (int qq = 0; qq < 4; qq++) {
            int idx = tid + qq * 256;
            int kk = idx & 15, m = idx >> 4;
            As[kk][m] = A2[m * 2 * Hn + k0 + kk];
            Bs[kk][m] = B2[(n0 + m) * 2 * Hn + k0 + kk];
        }
        __syncthreads();
#pragma unroll
        for (int kk = 0; kk < 16; kk++) {
            float4 a4 = *reinterpret_cast<const float4*>(&As[kk][ty * 4]);
            float4 b4 = *reinterpret_cast<const float4*>(&Bs[kk][tx * 4]);
            float av[4] = {a4.x, a4.y, a4.z, a4.w};
            float bv[4] = {b4.x, b4.y, b4.z, b4.w};
#pragma unroll
            for (int i = 0; i < 4; i++)
#pragma unroll
                for (int j = 0; j < 4; j++)
                    acc[i][j] += av[i] * bv[j];
        }
        __syncthreads();
    }
#pragma unroll
    for (int i = 0; i < 4; i++) {
        int row = ty * 4 + i;
#pragma unroll
        for (int j = 0; j < 4; j++)
            C[row * Cv + n0 + tx * 4 + j] = acc[i][j];
    }
}

// ---------------- encoder recurrence: all-512-row bf16 smem weight cache -------------
__global__ void __launch_bounds__(512, 1)
encoder_rec()
{
    extern __shared__ __align__(16) __nv_bfloat16 ws[];     // [512][128] bf16
    __shared__ __align__(16) float h_sm[Hn];
    __shared__ float c_sm[Hn];
    __shared__ float gate_sm[G4H];
    int b = blockIdx.x, dir = blockIdx.y;
    int tid = threadIdx.x;
    int g = tid >> 3, q = tid & 7;

    {
        const uint4* src = reinterpret_cast<const uint4*>(&g_eWbf[dir][0][0]);
        uint4* dst = reinterpret_cast<uint4*>(ws);
        for (int idx = tid; idx < G4H * 128 / 8; idx += 512) dst[idx] = src[idx];
    }
    if (tid < Hn) { h_sm[tid] = 0.f; c_sm[tid] = 0.f; }
    __syncthreads();

    const float4* h4 = reinterpret_cast<const float4*>(h_sm);

    for (int step = 0; step < Sn; step++) {
        int t = dir ? (Sn - 1 - step) : step;
        float4 H0 = h4[2*q], H1 = h4[2*q+1], H2 = h4[2*q+16], H3 = h4[2*q+17];
#pragma unroll
        for (int p = 0; p < 8; p++) {
            int r = p * 64 + g;
            const uint4* wr = reinterpret_cast<const uint4*>(ws + r * 128);
            float acc = dot8(wr[q], H0, H1) + dot8(wr[q + 8], H2, H3);
            acc = gred8(acc);
            if (q == 0) gate_sm[r] = acc + g_xpre[dir][t][b][r];
        }
        __syncthreads();
        if (tid < Hn) {
            float gi = gate_sm[tid], gf = gate_sm[tid + 128];
            float gg = gate_sm[tid + 256], go = gate_sm[tid + 384];
            float c = sigf(gf) * c_sm[tid] + sigf(gi) * tanhf(gg);
            float h = sigf(go) * tanhf(c);
            c_sm[tid] = c; h_sm[tid] = h;
            int j = dir * Hn + tid;
            g_hs[t][b][j] = h;
            g_hsT_bf[b][j][t] = __float2bfloat16(h);
        }
        __syncthreads();
    }
}

// ---------------- cluster-pair persistent decoder ------------------------------------
__global__ void __launch_bounds__(512, 1) __cluster_dims__(2, 1, 1)
decoder_persist(const float* __restrict__ mask, const float* __restrict__ va,
                const float* __restrict__ ua,
                const float* __restrict__ bih, const float* __restrict__ bhh)
{
    extern __shared__ __align__(16) __nv_bfloat16 dyn[];
    __nv_bfloat16* wc   = dyn;                                     // [128][WC_STRIDE]
    __nv_bfloat16* wa   = dyn + 128 * WC_STRIDE;                   // [256][WA_STRIDE]
    __nv_bfloat16* vasm = dyn + 128 * WC_STRIDE + 256 * WA_STRIDE; // [128][VA_STRIDE]

    __shared__ __align__(16) float s_sm[2][Hn];
    __shared__ __align__(16) float y_sm[64];
    __shared__ __align__(16) float vas_sm[Hn];
    __shared__ __align__(16) float u_sm[Hn];
    __shared__ __align__(16) float e_sm[256];
    __shared__ __align__(16) float ctxp_sm[2*Hn];
    __shared__ __align__(16) float xin_sm[384];
    __shared__ __align__(16) float mask_sm[256];
    __shared__ __align__(16) float bias_sm[256];
    __shared__ __align__(16) float gates_sm[256];
    __shared__ __align__(16) float xch_ctx[2][2*Hn];
    __shared__ __align__(16) float xch_s[2];
    __shared__ float red[16];
    __shared__ float S_loc[2];

    uint32_t rank;
    asm("mov.u32 %0, %%cluster_ctarank;" : "=r"(rank));
    int h = (int)rank;
    int b = blockIdx.x >> 1;
    int tid = threadIdx.x;
    int w = tid >> 5, l = tid & 31;
    int g = tid >> 3, q = tid & 7;

    uint32_t peer_xctx = mapa_peer(smem_u32(&xch_ctx[0][0]), rank ^ 1);
    uint32_t peer_xs   = mapa_peer(smem_u32(&xch_s[0]),      rank ^ 1);
    uint32_t peer_s    = mapa_peer(smem_u32(&s_sm[0][0]),    rank ^ 1);

    for (int idx = tid; idx < 128 * 384; idx += 512) {
        int lr = idx / 384, c = idx - lr * 384;
        int r = (lr >> 6) * 128 + h * 64 + (lr & 63);
        wc[lr * WC_STRIDE + c] = g_Wbf[r][c];
    }
    for (int idx = tid; idx < 256 * 128; idx += 512) {
        int sl = idx >> 7, c = idx & 127;
        wa[sl * WA_STRIDE + c] = g_wahsT_bf[b][h * 256 + sl][c];
    }
    for (int idx = tid; idx < 128 * 128; idx += 512) {
        int r = idx >> 7, c = idx & 127;
        vasm[r * VA_STRIDE + c] = __float2bfloat16(va[idx]);
    }
    if (tid < 256) {
        int r = (tid >> 6) * 128 + h * 64 + (tid & 63);
        bias_sm[tid] = bih[r] + bhh[r];
        mask_sm[tid] = mask[(h * 256 + tid) * Bn + b];
    }
    if (tid < Hn) { u_sm[tid] = ua[tid]; s_sm[0][tid] = 0.f; }
    if (tid < 64) y_sm[tid] = 0.f;
    __syncthreads();

    const uint4* hsT_bf4 = reinterpret_cast<const uint4*>(&g_hsT_bf[0][0][0]);
    const float4* u4   = reinterpret_cast<const float4*>(u_sm);
    const float4* vas4 = reinterpret_cast<const float4*>(vas_sm);
    const float4* e4p  = reinterpret_cast<const float4*>(e_sm);
    const float4* xin4 = reinterpret_cast<const float4*>(xin_sm);

    for (int t = 0; t < Tn; t++) {
        int par = t & 1;
        const float4* s4 = reinterpret_cast<const float4*>(&s_sm[par][0]);

        // ---- vas ----
        {
            float4 S0 = s4[2*q], S1 = s4[2*q+1], S2 = s4[2*q+16], S3 = s4[2*q+17];
#pragma unroll
            for (int p = 0; p < 2; p++) {
                int j = p * 64 + g;
                const uint4* wr = reinterpret_cast<const uint4*>(vasm + j * VA_STRIDE);
                float acc = dot8(wr[q], S0, S1) + dot8(wr[q + 8], S2, S3);
                acc = gred8(acc);
                if (q == 0) vas_sm[j] = acc;
            }
        }
        __syncthreads();                                        // sync 1

        // ---- scores + exp + warp sums ----
        {
            float4 V0 = vas4[2*q], V1 = vas4[2*q+1], V2 = vas4[2*q+16], V3 = vas4[2*q+17];
            float4 U0 = u4[2*q],   U1 = u4[2*q+1],   U2 = u4[2*q+16],   U3 = u4[2*q+17];
            float stacc = 0.f;
#pragma unroll
            for (int p = 0; p < 4; p++) {
                int sl = p * 64 + g;
                const uint4* ar = reinterpret_cast<const uint4*>(wa + sl * WA_STRIDE);
                float acc = tdot8(ar[q], V0, V1, U0, U1) + tdot8(ar[q + 8], V2, V3, U2, U3);
                acc = gred8(acc);
                float ex = __expf(acc * mask_sm[sl]);
                if (q == 0) e_sm[sl] = ex;
                stacc += ex;
            }
            stacc += __shfl_xor_sync(0xFFFFFFFFu, stacc, 8);
            stacc += __shfl_xor_sync(0xFFFFFFFFu, stacc, 16);
            if (l == 0) red[w] = stacc;
        }
        __syncthreads();                                        // sync 2

        // ---- partial ctx: hsT bf16 from L2 ----
        if (tid == 0) {
            float ss = red[0];
#pragma unroll
            for (int i = 1; i < 16; i++) ss += red[i];
            S_loc[par] = ss;
        }
        {
            float4 A0[4], A1[4];
#pragma unroll
            for (int k = 0; k < 4; k++) {
                A0[k] = e4p[2 * (q + 8 * k)];
                A1[k] = e4p[2 * (q + 8 * k) + 1];
            }
#pragma unroll
            for (int p = 0; p < 4; p++) {
                int j = p * 64 + g;
                // row j: 512 bf16 = 64 uint4; my s-half starts at uint4 h*32
                const uint4* hp = &hsT_bf4[(b * 2 * Hn + j) * 64 + h * 32];
                float acc = 0.f;
#pragma unroll
                for (int k = 0; k < 4; k++) {
                    uint4 H = __ldg(&hp[q + k * 8]);
                    acc += dot8(H, A0[k], A1[k]);
                }
                acc = gred8(acc);
                if (q == 0) ctxp_sm[j] = acc;
            }
        }
        __syncthreads();                                        // sync 3

        // ---- exchange ----
        if (tid < 256) st_remote_f32(peer_xctx + (par * 256 + tid) * 4, ctxp_sm[tid]);
        if (tid == 0)  st_remote_f32(peer_xs + par * 4, S_loc[par]);
        cluster_barrier();                                      // cluster 1

        // ---- xin ----
        if (tid < 128) xin_sm[tid] = s_sm[par][tid];
        else if (tid < 384) {
            int j = tid - 128;
            float inv = 1.f / (S_loc[par] + xch_s[par]);
            xin_sm[tid] = (ctxp_sm[j] + xch_ctx[par][j]) * inv;
        }
        __syncthreads();                                        // sync 4
        if (t == Tn - 1 && h == 0 && tid < 256) g_ctx[b][tid] = xin_sm[128 + tid];

        // ---- gates ----
        {
            float4 X[12];
#pragma unroll
            for (int o2 = 0; o2 < 6; o2++) {
                X[2*o2]   = xin4[2 * (q + 8 * o2)];
                X[2*o2+1] = xin4[2 * (q + 8 * o2) + 1];
            }
#pragma unroll
            for (int p = 0; p < 4; p++) {
                int lr = p * 64 + g;
                float acc = 0.f;
                if (p < 2) {
                    const uint4* wr = reinterpret_cast<const uint4*>(wc + lr * WC_STRIDE);
#pragma unroll
                    for (int o2 = 0; o2 < 6; o2++)
                        acc += dot8(wr[q + 8 * o2], X[2*o2], X[2*o2+1]);
                } else {
                    int r = p * 128 + h * 64 + g;
                    const uint4* wr = reinterpret_cast<const uint4*>(&g_Wbf[r][0]);
#pragma unroll
                    for (int o2 = 0; o2 < 6; o2++)
                        acc += dot8(__ldg(&wr[q + 8 * o2]), X[2*o2], X[2*o2+1]);
                }
                acc = gred8(acc);
                if (q == 0) gates_sm[lr] = acc + bias_sm[lr];
            }
        }
        __syncthreads();                                        // sync 5

        // ---- cell ----
        if (tid < 64) {
            float gi = gates_sm[tid],       gf = gates_sm[64 + tid];
            float gg = gates_sm[128 + tid], go = gates_sm[192 + tid];
            float y = sigf(gf) * y_sm[tid] + sigf(gi) * tanhf(gg);
            float s = sigf(go) * tanhf(y);
            y_sm[tid] = y;
            int jg = h * 64 + tid;
            s_sm[par ^ 1][jg] = s;
            st_remote_f32(peer_s + ((par ^ 1) * 128 + jg) * 4, s);
            if (t == Tn - 1) g_sfin[b][jg] = s;
        }
        cluster_barrier();                                      // cluster 2
    }
}

// ---------------- final softmax over C=32000 -----------------------------------------
__global__ void softmax_stat(const float* __restrict__ out)
{
    int b = blockIdx.x, tid = threadIdx.x;
    __shared__ float red[256];
    const float* row = out + b * Cv;
    float m = -1e30f;
    for (int i = tid; i < Cv; i += 256) m = fmaxf(m, row[i]);
    red[tid] = m; __syncthreads();
#pragma unroll
    for (int st = 128; st; st >>= 1) {
        if (tid < st) red[tid] = fmaxf(red[tid], red[tid + st]);
        __syncthreads();
    }
    m = red[0]; __syncthreads();
    float s = 0.f;
    for (int i = tid; i < Cv; i += 256) s += __expf(row[i] - m);
    red[tid] = s; __syncthreads();
#pragma unroll
    for (int st = 128; st; st >>= 1) {
        if (tid < st) red[tid] += red[tid + st];
        __syncthreads();
    }
    if (tid == 0) { g_rowstat[b][0] = m; g_rowstat[b][1] = 1.f / red[0]; }
}

__global__ void softmax_norm(float* out)
{
    int b = blockIdx.y;
    int i = blockIdx.x * 256 + threadIdx.x;
    float* row = out + b * Cv;
    row[i] = __expf(row[i] - g_rowstat[b][0]) * g_rowstat[b][1];
}

// ---------------- launch -------------------------------------------------------------
extern "C" void kernel_launch(void* const* d_in, const int* in_sizes, int n_in,
                              void* d_out, int out_size)
{
    (void)in_sizes; (void)n_in; (void)out_size;
    const float* x      = (const float*)d_in[0];
    const float* mask   = (const float*)d_in[1];
    const float* eWih_f = (const float*)d_in[2];
    const float* eWhh_f = (const float*)d_in[3];
    const float* ebih_f = (const float*)d_in[4];
    const float* ebhh_f = (const float*)d_in[5];
    const float* eWih_b = (const float*)d_in[6];
    const float* eWhh_b = (const float*)d_in[7];
    const float* ebih_b = (const float*)d_in[8];
    const float* ebhh_b = (const float*)d_in[9];
    const float* dWih   = (const float*)d_in[10];
    const float* dWhh   = (const float*)d_in[11];
    const float* dbih   = (const float*)d_in[12];
    const float* dbhh   = (const float*)d_in[13];
    const float* w_a    = (const float*)d_in[14];
    const float* v_a    = (const float*)d_in[15];
    const float* u_a    = (const float*)d_in[16];
    const float* w_b    = (const float*)d_in[17];
    const float* v_b    = (const float*)d_in[18];
    float* out = (float*)d_out;

    float *p_xpre, *p_hs, *p_sfin, *p_ctx;
    cudaGetSymbolAddress((void**)&p_xpre, g_xpre);
    cudaGetSymbolAddress((void**)&p_hs,   g_hs);
    cudaGetSymbolAddress((void**)&p_sfin, g_sfin);
    cudaGetSymbolAddress((void**)&p_ctx,  g_ctx);

    cudaFuncSetAttribute(encoder_rec, cudaFuncAttributeMaxDynamicSharedMemorySize, ENC_DYN_SMEM);
    cudaFuncSetAttribute(decoder_persist, cudaFuncAttributeMaxDynamicSharedMemorySize, DEC_DYN_SMEM);

    // 0) bf16 conversions (decoder weights + encoder Whh)
    prep_bf16<<<768, 256>>>(dWih, dWhh, eWhh_f, eWhh_b);

    // 1) xpre = x @ Wih^T + biases
    sgemm_xpre<<<dim3(G4H / 128, Sn * Bn / 128, 2), 256>>>(
        x, eWih_f, eWih_b, ebih_f, ebhh_f, ebih_b, ebhh_b, p_xpre);

    // 2) encoder recurrence (all-512-row bf16 smem weights; writes g_hs + g_hsT_bf)
    encoder_rec<<<dim3(Bn, 2), 512, ENC_DYN_SMEM>>>();

    // 3) wa_hs -> bf16 transposed
    sgemm_wahsT<<<dim3(1, Sn * Bn / 128), 256>>>(p_hs, w_a);

    // 4) cluster-pair decoder (smem bf16 constants, bf16 hsT stream)
    decoder_persist<<<2 * Bn, 512, DEC_DYN_SMEM>>>(mask, v_a, u_a, dbih, dbhh);

    // 5) logits + softmax
    gemm_logits<<<dim3(Cv / 64, 1), 256>>>(p_sfin, w_b, p_ctx, v_b, out);
    softmax_stat<<<Bn, 256>>>(out);
    softmax_norm<<<dim3(Cv / 256, Bn), 256>>>(out);
}